// round 3
// baseline (speedup 1.0000x reference)
#include <cuda_runtime.h>
#include <math.h>

#define NN_MAX 50000
#define EE_MAX 800000
#define IN_F   256
#define OUT_F  128
#define NHEAD  4
#define DHEAD  32

// ---------------- device scratch (static, no allocation) ----------------
__device__ float g_Wt[IN_F * OUT_F];                 // W transposed [k][o]
__device__ float g_Wx[(size_t)NN_MAX * OUT_F];       // x @ W.T
__device__ float g_ssrc[NN_MAX * NHEAD];
__device__ float g_sdst[NN_MAX * NHEAD];
__device__ int   g_deg[NN_MAX];
__device__ int   g_off[NN_MAX + 1];
__device__ int   g_cur[NN_MAX];
__device__ int   g_csr_src[EE_MAX];

// ---------------- f32x2 packed math helpers (sm_103a FFMA2) ----------------
__device__ __forceinline__ unsigned long long pack_dup(float v) {
    unsigned long long r;
    asm("mov.b64 %0, {%1, %1};" : "=l"(r) : "f"(v));
    return r;
}
__device__ __forceinline__ unsigned long long fma2(unsigned long long a,
                                                   unsigned long long b,
                                                   unsigned long long c) {
    unsigned long long d;
    asm("fma.rn.f32x2 %0, %1, %2, %3;" : "=l"(d) : "l"(a), "l"(b), "l"(c));
    return d;
}
__device__ __forceinline__ void unpack2(unsigned long long p, float& lo, float& hi) {
    asm("mov.b64 {%0, %1}, %2;" : "=f"(lo), "=f"(hi) : "l"(p));
}

__device__ __forceinline__ float lrelu02(float v) {
    return v > 0.f ? v : 0.2f * v;
}

// ---------------- K0: prep — transpose W + zero degree counters ----------------
__global__ void k_prep(const float* __restrict__ W, int Nn) {
    int i = blockIdx.x * 256 + threadIdx.x;
    if (i < IN_F * OUT_F) {
        int o = i / IN_F;
        int k = i % IN_F;
        g_Wt[k * OUT_F + o] = W[i];
    }
    if (i < Nn) g_deg[i] = 0;
}

// ---------------- K1: count in-degree per dst ----------------
__global__ void k_count(const int* __restrict__ ei, int Ee) {
    int e = blockIdx.x * 256 + threadIdx.x;
    if (e < Ee) atomicAdd(&g_deg[ei[Ee + e]], 1);
}

// ---------------- K2: single-block exclusive scan of degrees ----------------
__global__ void k_scan(int Nn) {
    __shared__ int partial[1024];
    int t = threadIdx.x;
    int chunk = (Nn + 1023) >> 10;
    int start = t * chunk;
    int end = min(start + chunk, Nn);
    int s = 0;
    for (int i = start; i < end; i++) s += g_deg[i];
    partial[t] = s;
    __syncthreads();
    // inclusive smem scan
    for (int off = 1; off < 1024; off <<= 1) {
        int add = (t >= off) ? partial[t - off] : 0;
        __syncthreads();
        partial[t] += add;
        __syncthreads();
    }
    int run = (t == 0) ? 0 : partial[t - 1];
    for (int i = start; i < end; i++) {
        g_off[i] = run;
        g_cur[i] = run;
        run += g_deg[i];
    }
    if (start < Nn && end == Nn) g_off[Nn] = run;
}

// ---------------- K3: scatter src ids into CSR order ----------------
__global__ void k_scatter(const int* __restrict__ ei, int Ee) {
    int e = blockIdx.x * 256 + threadIdx.x;
    if (e >= Ee) return;
    int s = ei[e];
    int d = ei[Ee + e];
    int pos = atomicAdd(&g_cur[d], 1);
    g_csr_src[pos] = s;
}

// ---------------- K4: GEMM (f32x2) + fused attention scores ----------------
__global__ void __launch_bounds__(256, 1)
k_gemm(const float* __restrict__ x, const float* __restrict__ a_w, int Nn) {
    extern __shared__ float sm[];
    float* Wt_s = sm;                 // IN_F*OUT_F
    float* x_s  = sm + IN_F * OUT_F;  // 64*IN_F

    int tid  = threadIdx.x;
    int lane = tid & 31;
    int wid  = tid >> 5;
    int n0   = blockIdx.x * 64;

    {
        const float4* src = (const float4*)g_Wt;
        float4* dst = (float4*)Wt_s;
        #pragma unroll
        for (int i = tid; i < IN_F * OUT_F / 4; i += 256) dst[i] = src[i];
    }
    {
        float4* dst = (float4*)x_s;
        const float4* src = (const float4*)x;
        #pragma unroll
        for (int i = tid; i < 64 * IN_F / 4; i += 256) {
            int row = i >> 6;
            int col = i & 63;
            int gr = n0 + row;
            dst[i] = (gr < Nn) ? src[(size_t)gr * 64 + col]
                               : make_float4(0.f, 0.f, 0.f, 0.f);
        }
    }
    __syncthreads();

    unsigned long long acc[8][2];
    #pragma unroll
    for (int r = 0; r < 8; r++) { acc[r][0] = 0ull; acc[r][1] = 0ull; }

    int o0 = lane << 2;
    const float* xrow = x_s + (wid * 8) * IN_F;

    #pragma unroll 4
    for (int k = 0; k < IN_F; k++) {
        ulonglong2 w2 = *(const ulonglong2*)(Wt_s + k * OUT_F + o0);
        #pragma unroll
        for (int r = 0; r < 8; r++) {
            unsigned long long xp = pack_dup(xrow[r * IN_F + k]);
            acc[r][0] = fma2(xp, w2.x, acc[r][0]);
            acc[r][1] = fma2(xp, w2.y, acc[r][1]);
        }
    }

    float4 as4 = *(const float4*)(a_w + (lane & 7) * 4);
    float4 ad4 = *(const float4*)(a_w + DHEAD + (lane & 7) * 4);
    int h = lane >> 3;

    #pragma unroll
    for (int r = 0; r < 8; r++) {
        int gr = n0 + wid * 8 + r;
        if (gr < Nn) {
            float f0, f1, f2, f3;
            unpack2(acc[r][0], f0, f1);
            unpack2(acc[r][1], f2, f3);
            *(float4*)(g_Wx + (size_t)gr * OUT_F + o0) = make_float4(f0, f1, f2, f3);
            float p1 = f0 * as4.x + f1 * as4.y + f2 * as4.z + f3 * as4.w;
            float p2 = f0 * ad4.x + f1 * ad4.y + f2 * ad4.z + f3 * ad4.w;
            #pragma unroll
            for (int off = 4; off; off >>= 1) {
                p1 += __shfl_xor_sync(0xffffffffu, p1, off);
                p2 += __shfl_xor_sync(0xffffffffu, p2, off);
            }
            if ((lane & 7) == 0) {
                g_ssrc[gr * NHEAD + h] = p1;
                g_sdst[gr * NHEAD + h] = p2;
            }
        }
    }
}

// ---------------- K5: gather-aggregate + softmax-normalize + ELU ----------------
// Warp per dst node. out[n] = elu( (sum_e e_exp * Wx[src_e]) / (sum_e e_exp + 1e-8) )
__global__ void __launch_bounds__(256)
k_gather(float* __restrict__ out, int Nn) {
    int n = (blockIdx.x * blockDim.x + threadIdx.x) >> 5;
    if (n >= Nn) return;
    int lane = threadIdx.x & 31;
    int h = lane >> 3;

    float sd = g_sdst[n * NHEAD + h];
    int beg = g_off[n];
    int end = g_off[n + 1];

    float4 acc = make_float4(0.f, 0.f, 0.f, 0.f);
    float den = 0.f;

    for (int base = beg; base < end; base += 32) {
        int my = base + lane;
        int src_l = (my < end) ? g_csr_src[my] : 0;
        int cnt = min(32, end - base);
        int j = 0;
        // 2-way unrolled for MLP
        for (; j + 1 < cnt; j += 2) {
            int s0 = __shfl_sync(0xffffffffu, src_l, j);
            int s1 = __shfl_sync(0xffffffffu, src_l, j + 1);
            float ss0 = g_ssrc[s0 * NHEAD + h];
            float ss1 = g_ssrc[s1 * NHEAD + h];
            float4 w0 = *(const float4*)(g_Wx + (size_t)s0 * OUT_F + lane * 4);
            float4 w1 = *(const float4*)(g_Wx + (size_t)s1 * OUT_F + lane * 4);
            float e0 = __expf(lrelu02(ss0 + sd));
            float e1 = __expf(lrelu02(ss1 + sd));
            acc.x += e0 * w0.x; acc.y += e0 * w0.y;
            acc.z += e0 * w0.z; acc.w += e0 * w0.w;
            acc.x += e1 * w1.x; acc.y += e1 * w1.y;
            acc.z += e1 * w1.z; acc.w += e1 * w1.w;
            den += e0 + e1;
        }
        for (; j < cnt; j++) {
            int s0 = __shfl_sync(0xffffffffu, src_l, j);
            float ss0 = g_ssrc[s0 * NHEAD + h];
            float4 w0 = *(const float4*)(g_Wx + (size_t)s0 * OUT_F + lane * 4);
            float e0 = __expf(lrelu02(ss0 + sd));
            acc.x += e0 * w0.x; acc.y += e0 * w0.y;
            acc.z += e0 * w0.z; acc.w += e0 * w0.w;
            den += e0;
        }
    }

    float inv = 1.f / (den + 1e-8f);
    acc.x *= inv; acc.y *= inv; acc.z *= inv; acc.w *= inv;
    acc.x = acc.x > 0.f ? acc.x : expm1f(acc.x);
    acc.y = acc.y > 0.f ? acc.y : expm1f(acc.y);
    acc.z = acc.z > 0.f ? acc.z : expm1f(acc.z);
    acc.w = acc.w > 0.f ? acc.w : expm1f(acc.w);
    *(float4*)(out + (size_t)n * OUT_F + lane * 4) = acc;
}

// ---------------- launch ----------------
extern "C" void kernel_launch(void* const* d_in, const int* in_sizes, int n_in,
                              void* d_out, int out_size) {
    const float* x   = (const float*)d_in[0];
    const int*   ei  = (const int*)d_in[1];
    const float* W   = (const float*)d_in[2];
    const float* a_w = (const float*)d_in[3];
    float* out = (float*)d_out;

    int Nn = in_sizes[0] / IN_F;
    int Ee = in_sizes[1] / 2;

    const int smem_gemm = (IN_F * OUT_F + 64 * IN_F) * sizeof(float);
    cudaFuncSetAttribute(k_gemm, cudaFuncAttributeMaxDynamicSharedMemorySize, smem_gemm);

    int prep_n = (Nn > IN_F * OUT_F) ? Nn : IN_F * OUT_F;
    k_prep<<<(prep_n + 255) / 256, 256>>>(W, Nn);
    k_count<<<(Ee + 255) / 256, 256>>>(ei, Ee);
    k_scan<<<1, 1024>>>(Nn);
    k_scatter<<<(Ee + 255) / 256, 256>>>(ei, Ee);
    k_gemm<<<(Nn + 63) / 64, 256, smem_gemm>>>(x, a_w, Nn);
    k_gather<<<(Nn * 32 + 255) / 256, 256>>>(out, Nn);
}

// round 7
// speedup vs baseline: 1.0633x; 1.0633x over previous
#include <cuda_runtime.h>
#include <math.h>

#define NN_MAX 50000
#define EE_MAX 800000
#define IN_F   256
#define OUT_F  128
#define NHEAD  4
#define DHEAD  32

// ---------------- device scratch (static, no allocation) ----------------
__device__ __align__(16) float g_Wt[IN_F * OUT_F];            // W transposed [k][o]
__device__ __align__(16) float g_Wx[(size_t)NN_MAX * OUT_F];  // x @ W.T
__device__ __align__(16) float g_ssrc[NN_MAX * NHEAD];
__device__ __align__(16) float g_sdst[NN_MAX * NHEAD];
__device__ __align__(16) int   g_deg[NN_MAX + 4];
__device__ __align__(16) int   g_off[NN_MAX + 4];
__device__ __align__(16) int   g_cur[NN_MAX + 4];
__device__ __align__(16) int   g_csr_src[EE_MAX];
__device__ __align__(16) float g_csr_e[(size_t)EE_MAX * NHEAD];

// ---------------- f32x2 packed math helpers (sm_103a FFMA2) ----------------
__device__ __forceinline__ unsigned long long pack_dup(float v) {
    unsigned long long r;
    asm("mov.b64 %0, {%1, %1};" : "=l"(r) : "f"(v));
    return r;
}
__device__ __forceinline__ unsigned long long fma2(unsigned long long a,
                                                   unsigned long long b,
                                                   unsigned long long c) {
    unsigned long long d;
    asm("fma.rn.f32x2 %0, %1, %2, %3;" : "=l"(d) : "l"(a), "l"(b), "l"(c));
    return d;
}
__device__ __forceinline__ void unpack2(unsigned long long p, float& lo, float& hi) {
    asm("mov.b64 {%0, %1}, %2;" : "=f"(lo), "=f"(hi) : "l"(p));
}

__device__ __forceinline__ float lrelu02(float v) {
    return v > 0.f ? v : 0.2f * v;
}

// ---------------- K1: count in-degree (int4) + W transpose (fused) ----------------
__global__ void k_count_tr(const int* __restrict__ ei, const float* __restrict__ W, int Ee) {
    int i = blockIdx.x * 256 + threadIdx.x;
    int base = i * 4;
    if (base + 3 < Ee) {
        int4 d4 = *(const int4*)(ei + Ee + base);
        atomicAdd(&g_deg[d4.x], 1);
        atomicAdd(&g_deg[d4.y], 1);
        atomicAdd(&g_deg[d4.z], 1);
        atomicAdd(&g_deg[d4.w], 1);
    } else if (base < Ee) {
        for (int k = base; k < Ee; k++) atomicAdd(&g_deg[ei[Ee + k]], 1);
    }
    if (i < IN_F * OUT_F) {
        int o = i / IN_F;
        int k = i % IN_F;
        g_Wt[k * OUT_F + o] = W[i];
    }
}

// ---------------- K2: single-block exclusive scan (int4 + Kogge-Stone) ----------------
__global__ void __launch_bounds__(1024) k_scan(int Nn) {
    __shared__ int psum[1024];
    int t = threadIdx.x;
    int nv = (Nn + 3) >> 2;               // number of int4 groups
    int per = (nv + 1023) >> 10;
    int v0 = t * per;
    int v1 = min(v0 + per, nv);
    const int4* deg4 = (const int4*)g_deg;
    int s = 0;
    for (int i = v0; i < v1; i++) {
        int4 q = deg4[i];
        s += q.x + q.y + q.z + q.w;
    }
    psum[t] = s;
    __syncthreads();
    for (int off = 1; off < 1024; off <<= 1) {
        int add = (t >= off) ? psum[t - off] : 0;
        __syncthreads();
        psum[t] += add;
        __syncthreads();
    }
    int run = t ? psum[t - 1] : 0;
    for (int i = v0; i < v1; i++) {
        int4 q = deg4[i];
        int4 o;
        o.x = run; run += q.x;
        o.y = run; run += q.y;
        o.z = run; run += q.z;
        o.w = run; run += q.w;
        ((int4*)g_off)[i] = o;
        ((int4*)g_cur)[i] = o;
    }
    if (v0 < nv && v1 == nv) g_off[Nn] = run;
}

// ---------------- K3: scatter src ids + per-edge exp scores into CSR order ----------------
__global__ void k_scatter_e(const int* __restrict__ ei, int Ee) {
    int e = blockIdx.x * 256 + threadIdx.x;
    if (e >= Ee) return;
    int s = ei[e];
    int d = ei[Ee + e];
    float4 ss = *(const float4*)(g_ssrc + s * 4);
    float4 sd = *(const float4*)(g_sdst + d * 4);
    float4 v;
    v.x = __expf(lrelu02(ss.x + sd.x));
    v.y = __expf(lrelu02(ss.y + sd.y));
    v.z = __expf(lrelu02(ss.z + sd.z));
    v.w = __expf(lrelu02(ss.w + sd.w));
    int pos = atomicAdd(&g_cur[d], 1);
    g_csr_src[pos] = s;
    *(float4*)(g_csr_e + (size_t)pos * 4) = v;
}

// ---------------- K4: GEMM (f32x2) + fused attention scores ----------------
__global__ void __launch_bounds__(256, 1)
k_gemm(const float* __restrict__ x, const float* __restrict__ a_w, int Nn) {
    extern __shared__ float sm[];
    float* Wt_s = sm;                 // IN_F*OUT_F
    float* x_s  = sm + IN_F * OUT_F;  // 64*IN_F

    int tid  = threadIdx.x;
    int lane = tid & 31;
    int wid  = tid >> 5;
    int n0   = blockIdx.x * 64;

    {
        const float4* src = (const float4*)g_Wt;
        float4* dst = (float4*)Wt_s;
        #pragma unroll
        for (int i = tid; i < IN_F * OUT_F / 4; i += 256) dst[i] = src[i];
    }
    {
        float4* dst = (float4*)x_s;
        const float4* src = (const float4*)x;
        #pragma unroll
        for (int i = tid; i < 64 * IN_F / 4; i += 256) {
            int row = i >> 6;
            int col = i & 63;
            int gr = n0 + row;
            dst[i] = (gr < Nn) ? src[(size_t)gr * 64 + col]
                               : make_float4(0.f, 0.f, 0.f, 0.f);
        }
    }
    __syncthreads();

    unsigned long long acc[8][2];
    #pragma unroll
    for (int r = 0; r < 8; r++) { acc[r][0] = 0ull; acc[r][1] = 0ull; }

    int o0 = lane << 2;
    const float* xrow = x_s + (wid * 8) * IN_F;

    #pragma unroll 4
    for (int k = 0; k < IN_F; k++) {
        ulonglong2 w2 = *(const ulonglong2*)(Wt_s + k * OUT_F + o0);
        #pragma unroll
        for (int r = 0; r < 8; r++) {
            unsigned long long xp = pack_dup(xrow[r * IN_F + k]);
            acc[r][0] = fma2(xp, w2.x, acc[r][0]);
            acc[r][1] = fma2(xp, w2.y, acc[r][1]);
        }
    }

    float4 as4 = *(const float4*)(a_w + (lane & 7) * 4);
    float4 ad4 = *(const float4*)(a_w + DHEAD + (lane & 7) * 4);
    int h = lane >> 3;

    #pragma unroll
    for (int r = 0; r < 8; r++) {
        int gr = n0 + wid * 8 + r;
        if (gr < Nn) {
            float f0, f1, f2, f3;
            unpack2(acc[r][0], f0, f1);
            unpack2(acc[r][1], f2, f3);
            *(float4*)(g_Wx + (size_t)gr * OUT_F + o0) = make_float4(f0, f1, f2, f3);
            float p1 = f0 * as4.x + f1 * as4.y + f2 * as4.z + f3 * as4.w;
            float p2 = f0 * ad4.x + f1 * ad4.y + f2 * ad4.z + f3 * ad4.w;
            #pragma unroll
            for (int off = 4; off; off >>= 1) {
                p1 += __shfl_xor_sync(0xffffffffu, p1, off);
                p2 += __shfl_xor_sync(0xffffffffu, p2, off);
            }
            if ((lane & 7) == 0) {
                g_ssrc[gr * NHEAD + h] = p1;
                g_sdst[gr * NHEAD + h] = p2;
            }
        }
    }
}

// ---------------- K5: gather-aggregate, warp per (node, head) ----------------
// out[n, h*32+lane] = elu( (sum_e e[edge][h] * Wx[src_e][h*32+lane]) / (sum_e e + 1e-8) )
__global__ void __launch_bounds__(256)
k_gather(float* __restrict__ out, int Nn) {
    int gw = (blockIdx.x * blockDim.x + threadIdx.x) >> 5;
    if (gw >= Nn * NHEAD) return;
    int lane = threadIdx.x & 31;
    int n = gw >> 2;
    int h = gw & 3;

    int beg = g_off[n];
    int end = g_off[n + 1];

    float acc0 = 0.f, acc1 = 0.f;
    float den = 0.f;
    const float* wxh = g_Wx + h * DHEAD + lane;

    for (int base = beg; base < end; base += 32) {
        int my = base + lane;
        bool valid = my < end;
        int   src_l = valid ? g_csr_src[my] : 0;
        float e_l   = valid ? g_csr_e[(size_t)my * 4 + h] : 0.f;
        den += e_l;
        int cnt = min(32, end - base);
        int j = 0;
        for (; j + 3 < cnt; j += 4) {
            int s0 = __shfl_sync(0xffffffffu, src_l, j);
            int s1 = __shfl_sync(0xffffffffu, src_l, j + 1);
            int s2 = __shfl_sync(0xffffffffu, src_l, j + 2);
            int s3 = __shfl_sync(0xffffffffu, src_l, j + 3);
            float e0 = __shfl_sync(0xffffffffu, e_l, j);
            float e1 = __shfl_sync(0xffffffffu, e_l, j + 1);
            float e2 = __shfl_sync(0xffffffffu, e_l, j + 2);
            float e3 = __shfl_sync(0xffffffffu, e_l, j + 3);
            float w0 = wxh[(size_t)s0 * OUT_F];
            float w1 = wxh[(size_t)s1 * OUT_F];
            float w2 = wxh[(size_t)s2 * OUT_F];
            float w3 = wxh[(size_t)s3 * OUT_F];
            acc0 = fmaf(e0, w0, acc0);
            acc1 = fmaf(e1, w1, acc1);
            acc0 = fmaf(e2, w2, acc0);
            acc1 = fmaf(e3, w3, acc1);
        }
        for (; j < cnt; j++) {
            int s0 = __shfl_sync(0xffffffffu, src_l, j);
            float e0 = __shfl_sync(0xffffffffu, e_l, j);
            float w0 = wxh[(size_t)s0 * OUT_F];
            acc0 = fmaf(e0, w0, acc0);
        }
    }

    float acc = acc0 + acc1;
    #pragma unroll
    for (int off = 16; off; off >>= 1)
        den += __shfl_xor_sync(0xffffffffu, den, off);

    float v = acc / (den + 1e-8f);
    v = v > 0.f ? v : expm1f(v);
    out[(size_t)n * OUT_F + h * DHEAD + lane] = v;
}

// ---------------- launch ----------------
extern "C" void kernel_launch(void* const* d_in, const int* in_sizes, int n_in,
                              void* d_out, int out_size) {
    const float* x   = (const float*)d_in[0];
    const int*   ei  = (const int*)d_in[1];
    const float* W   = (const float*)d_in[2];
    const float* a_w = (const float*)d_in[3];
    float* out = (float*)d_out;

    int Nn = in_sizes[0] / IN_F;
    int Ee = in_sizes[1] / 2;

    const int smem_gemm = (IN_F * OUT_F + 64 * IN_F) * sizeof(float);
    cudaFuncSetAttribute(k_gemm, cudaFuncAttributeMaxDynamicSharedMemorySize, smem_gemm);

    void* deg_ptr = nullptr;
    cudaGetSymbolAddress(&deg_ptr, g_deg);
    cudaMemsetAsync(deg_ptr, 0, sizeof(int) * (NN_MAX + 4));

    int cnt_threads = (Ee + 3) / 4;
    int cnt_grid = (max(cnt_threads, IN_F * OUT_F) + 255) / 256;
    k_count_tr<<<cnt_grid, 256>>>(ei, W, Ee);
    k_scan<<<1, 1024>>>(Nn);
    k_gemm<<<(Nn + 63) / 64, 256, smem_gemm>>>(x, a_w, Nn);
    k_scatter_e<<<(Ee + 255) / 256, 256>>>(ei, Ee);
    k_gather<<<(Nn * NHEAD * 32 + 255) / 256, 256>>>(out, Nn);
}